// round 11
// baseline (speedup 1.0000x reference)
#include <cuda_runtime.h>
#include <cstdint>

// ============================================================================
// LSTM_34883724378521 : T=60, C=H=128, N=4096, TOUT=114
// Strategy: precompute Z[t] = x_t @ W_ih^T for ALL t in one parallel GEMM
// (no sequential dependency), then run 114 identical K=128 recurrent steps:
//   phase 1: gates = h @ W_hh^T + Z[t] + b      (Z streamed via cp.async)
//   phase 2: gates = h @ (W_ih+W_hh)^T + b
// tf32 mma.sync, CTA tile M=128 x N=64, 256 threads, 2 CTAs/SM.
// ============================================================================
#define NB 4096
#define HD 128
#define NG 512
#define TMAX 60

__device__ __forceinline__ uint32_t smem_u32(const void* p) {
    uint32_t a;
    asm("{ .reg .u64 t; cvta.to.shared.u64 t, %1; cvt.u32.u64 %0, t; }"
        : "=r"(a) : "l"(p));
    return a;
}
__device__ __forceinline__ void cp16(uint32_t dst, const void* src) {
    asm volatile("cp.async.cg.shared.global [%0], [%1], 16;" :: "r"(dst), "l"(src));
}
#define CP_COMMIT() asm volatile("cp.async.commit_group;" ::: "memory")
#define CP_WAIT(n)  asm volatile("cp.async.wait_group %0;" :: "n"(n) : "memory")

__device__ __forceinline__ uint32_t rna_tf32(float v) {
    uint32_t u; asm("cvt.rna.tf32.f32 %0, %1;" : "=r"(u) : "f"(v)); return u;
}
__device__ __forceinline__ void mma8(float* d, const uint32_t* a, const uint32_t* b) {
    asm volatile(
        "mma.sync.aligned.m16n8k8.row.col.f32.tf32.tf32.f32 "
        "{%0,%1,%2,%3}, {%4,%5,%6,%7}, {%8,%9}, {%0,%1,%2,%3};"
        : "+f"(d[0]), "+f"(d[1]), "+f"(d[2]), "+f"(d[3])
        : "r"(a[0]), "r"(a[1]), "r"(a[2]), "r"(a[3]), "r"(b[0]), "r"(b[1]));
}
__device__ __forceinline__ float sigf(float x)   { return 1.0f / (1.0f + __expf(-x)); }
__device__ __forceinline__ float tanhf_(float x) { return 1.0f - 2.0f / (__expf(2.0f * x) + 1.0f); }

// ---------------------------------------------------------------------------
// persistent device state
// ---------------------------------------------------------------------------
__device__ float g_Hbuf0[HD * NB];     // h state, h-major [H][N] (tf32-rounded)
__device__ float g_Hbuf1[HD * NB];
__device__ float g_Cbuf [HD * NB];     // c state, h-major
__device__ float g_Whh[NG * HD];       // permuted W_hh, tf32-rounded
__device__ float g_Wih[NG * HD];       // permuted W_ih, tf32-rounded
__device__ float g_Wsum[NG * HD];      // permuted W_ih+W_hh, tf32-rounded
__device__ float g_bias[NG];           // permuted b_ih + b_hh
__device__ float g_Z[(size_t)TMAX * NG * NB];   // 503 MB scratch: x@W_ih^T

// ---------------------------------------------------------------------------
// prep: row perm r = 4*h+g <- g*128+h ; RNA-round weights; zero state
// ---------------------------------------------------------------------------
__global__ void prep_kernel(const float* __restrict__ Wih, const float* __restrict__ Whh,
                            const float* __restrict__ bih, const float* __restrict__ bhh) {
    int tid = blockIdx.x * 256 + threadIdx.x;       // 256*256 = 65536
    int r = tid >> 7, k = tid & 127;
    int h = r >> 2, g = r & 3;
    int orig = g * HD + h;
    float wi = Wih[orig * HD + k], wh = Whh[orig * HD + k];
    g_Wih [r * HD + k] = __uint_as_float(rna_tf32(wi));
    g_Whh [r * HD + k] = __uint_as_float(rna_tf32(wh));
    g_Wsum[r * HD + k] = __uint_as_float(rna_tf32(wi + wh));
    if (k == 0) g_bias[r] = bih[orig] + bhh[orig];
    for (int i = tid; i < HD * NB; i += 65536) {
        g_Hbuf0[i] = 0.0f;
        g_Cbuf[i]  = 0.0f;
    }
}

// ---------------------------------------------------------------------------
// smem layout (float offsets): bias(64) | 2x A(32x136) | 2x B(64x36) | Z(64x132)
// H2 stage (16 x 130) aliases A buffer 0 after the mainloop.
// ---------------------------------------------------------------------------
static constexpr int A_STR = 136, B_STR = 36, H_STR = 130, Z_STR = 132;
static constexpr int A_FL  = 32 * A_STR;      // 4352
static constexpr int B_FL  = 64 * B_STR;      // 2304
static constexpr int OFF_BIAS = 0;
static constexpr int OFF_A    = 64;
static constexpr int OFF_B    = OFF_A + 2 * A_FL;     // 8768
static constexpr int OFF_Z    = OFF_B + 2 * B_FL;     // 13376
static constexpr int SM_FLOATS = OFF_Z + 64 * Z_STR;  // 21824
static constexpr int SM_BYTES  = SM_FLOATS * 4;       // 87296 -> 2 CTAs/SM
static constexpr int SM_BYTES_PC = OFF_Z * 4;         // precompute: no Z tile

// ---------------------------------------------------------------------------
// shared mainloop: 4 chunks of K=32, 2 A bufs / 2 B bufs, prefetch dist 1.
// A from asrc [128][NB] at col n0 (DOCVT: round to tf32); B from W [NG][128].
// ---------------------------------------------------------------------------
template <bool DOCVT, bool HASZ>
__device__ __forceinline__ void gemm_mainloop(
    float acc[2][4][4], float* smf, uint32_t sb,
    const float* asrc, const float* W, const float* zt,
    int j, int n0, int tid, int wm, int wn, int gq, int tig) {

    auto loadC = [&](int ch) {
        const int buf = ch & 1;
        const uint32_t ab = sb + (uint32_t)(OFF_A + buf * A_FL) * 4;
        const uint32_t bb = sb + (uint32_t)(OFF_B + buf * B_FL) * 4;
        #pragma unroll
        for (int it = 0; it < 4; it++) {   // A: 32 k-rows x 128 m
            int idx = tid + it * 256;
            int kk = idx >> 5, mp = (idx & 31) << 2;
            cp16(ab + (uint32_t)(kk * A_STR + mp) * 4,
                 asrc + (size_t)(ch * 32 + kk) * NB + n0 + mp);
        }
        #pragma unroll
        for (int it = 0; it < 2; it++) {   // B: 64 gate-cols x 32 k
            int idx = tid + it * 256;
            int n = idx >> 3, q = (idx & 7) << 2;
            cp16(bb + (uint32_t)(n * B_STR + q) * 4,
                 W + (size_t)(j * 64 + n) * HD + ch * 32 + q);
        }
        CP_COMMIT();
    };

    loadC(0);
    if (HASZ) {                            // Z tile: 64 c-rows x 128 n
        #pragma unroll
        for (int it = 0; it < 8; it++) {
            int idx = tid + it * 256;
            int row = idx >> 5, q = (idx & 31) << 2;
            cp16(sb + (uint32_t)(OFF_Z + row * Z_STR + q) * 4,
                 zt + (size_t)row * NB + q);
        }
        CP_COMMIT();
    }

    #pragma unroll
    for (int ch = 0; ch < 4; ch++) {
        if (ch == 0 && HASZ) { CP_WAIT(1); } else { CP_WAIT(0); }
        __syncthreads();                   // chunk ch ready; mma(ch-1) done
        if (ch + 1 < 4) loadC(ch + 1);     // writes buf (ch+1)&1 (drained)
        const float* As = smf + OFF_A + (ch & 1) * A_FL;
        const float* Bs = smf + OFF_B + (ch & 1) * B_FL;

        #pragma unroll
        for (int kc = 0; kc < 4; kc++) {
            const int k0 = kc * 8;
            uint32_t a[2][4];
            #pragma unroll
            for (int mt = 0; mt < 2; mt++) {
                const int r0 = wm * 32 + mt * 16 + gq;
                float v0 = As[(k0 + tig) * A_STR + r0];
                float v1 = As[(k0 + tig) * A_STR + r0 + 8];
                float v2 = As[(k0 + tig + 4) * A_STR + r0];
                float v3 = As[(k0 + tig + 4) * A_STR + r0 + 8];
                if (DOCVT) {
                    a[mt][0] = rna_tf32(v0); a[mt][1] = rna_tf32(v1);
                    a[mt][2] = rna_tf32(v2); a[mt][3] = rna_tf32(v3);
                } else {
                    a[mt][0] = __float_as_uint(v0); a[mt][1] = __float_as_uint(v1);
                    a[mt][2] = __float_as_uint(v2); a[mt][3] = __float_as_uint(v3);
                }
            }
            #pragma unroll
            for (int nt = 0; nt < 4; nt++) {
                const int c0 = wn * 32 + nt * 8 + gq;
                uint32_t b[2];
                b[0] = __float_as_uint(Bs[c0 * B_STR + k0 + tig]);
                b[1] = __float_as_uint(Bs[c0 * B_STR + k0 + tig + 4]);
                mma8(acc[0][nt], a[0], b);
                mma8(acc[1][nt], a[1], b);
            }
        }
    }
    __syncthreads();                       // all mma done
}

// ---------------------------------------------------------------------------
// precompute: Z[t][c][n] = (x_t @ W_ih^T)[c][n] for all t. grid (8, 32, 60).
// ---------------------------------------------------------------------------
__global__ void __launch_bounds__(256, 2)
zprep_kernel(const float* __restrict__ img) {
    extern __shared__ float smf[];
    const uint32_t sb = smem_u32(smf);
    const int tid = threadIdx.x, lane = tid & 31, wid = tid >> 5;
    const int gq = lane >> 2, tig = lane & 3;
    const int wm = wid >> 1, wn = wid & 1;
    const int j = blockIdx.x, n0 = blockIdx.y * 128, t = blockIdx.z;

    float acc[2][4][4];
    #pragma unroll
    for (int a0 = 0; a0 < 2; a0++)
        #pragma unroll
        for (int a1 = 0; a1 < 4; a1++)
            #pragma unroll
            for (int a2 = 0; a2 < 4; a2++) acc[a0][a1][a2] = 0.0f;

    gemm_mainloop<true, false>(acc, smf, sb, img + (size_t)t * HD * NB,
                               g_Wih, nullptr, j, n0, tid, wm, wn, gq, tig);

    // direct scatter store: 8-lane 32B-coalesced along n
    const size_t zbase = ((size_t)t * NG + j * 64) * NB + n0;
    #pragma unroll
    for (int mt = 0; mt < 2; mt++) {
        const int r0 = wm * 32 + mt * 16 + gq;
        #pragma unroll
        for (int nt = 0; nt < 4; nt++) {
            const int c0 = wn * 32 + nt * 8 + 2 * tig;
            g_Z[zbase + (size_t)(c0    ) * NB + r0    ] = acc[mt][nt][0];
            g_Z[zbase + (size_t)(c0 + 1) * NB + r0    ] = acc[mt][nt][1];
            g_Z[zbase + (size_t)(c0    ) * NB + r0 + 8] = acc[mt][nt][2];
            g_Z[zbase + (size_t)(c0 + 1) * NB + r0 + 8] = acc[mt][nt][3];
        }
    }
}

// ---------------------------------------------------------------------------
// recurrent step (K=128 always). HASZ: add Z[t] tile to accumulators.
// ---------------------------------------------------------------------------
template <bool HASZ>
__global__ void __launch_bounds__(256, 2)
lstm_step(const float* __restrict__ zt,     // Z + offsets (or null)
          const float* __restrict__ W,      // g_Whh (p1) or g_Wsum (p2)
          const float* __restrict__ hprev,
          float* __restrict__ hnext,
          float* __restrict__ out, int t_out, int TOUT) {
    extern __shared__ float smf[];
    const uint32_t sb = smem_u32(smf);
    const int tid = threadIdx.x, lane = tid & 31, wid = tid >> 5;
    const int gq = lane >> 2, tig = lane & 3;
    const int wm = wid >> 1, wn = wid & 1;
    const int j = blockIdx.x, n0 = blockIdx.y * 128;

    if (tid < 64) smf[OFF_BIAS + tid] = g_bias[j * 64 + tid];

    float acc[2][4][4];
    #pragma unroll
    for (int a0 = 0; a0 < 2; a0++)
        #pragma unroll
        for (int a1 = 0; a1 < 4; a1++)
            #pragma unroll
            for (int a2 = 0; a2 < 4; a2++) acc[a0][a1][a2] = 0.0f;

    const float* ztile = HASZ ? (zt + (size_t)(j * 64) * NB + n0) : nullptr;
    gemm_mainloop<false, HASZ>(acc, smf, sb, hprev, W, ztile,
                               j, n0, tid, wm, wn, gq, tig);

    // ---- add Z (fragment positions, conflict-free LDS) ----
    if (HASZ) {
        const float* Zs = smf + OFF_Z;
        #pragma unroll
        for (int mt = 0; mt < 2; mt++) {
            const int r0 = wm * 32 + mt * 16 + gq;
            #pragma unroll
            for (int nt = 0; nt < 4; nt++) {
                const int c0 = wn * 32 + nt * 8 + 2 * tig;
                acc[mt][nt][0] += Zs[(c0    ) * Z_STR + r0    ];
                acc[mt][nt][1] += Zs[(c0 + 1) * Z_STR + r0    ];
                acc[mt][nt][2] += Zs[(c0    ) * Z_STR + r0 + 8];
                acc[mt][nt][3] += Zs[(c0 + 1) * Z_STR + r0 + 8];
            }
        }
    }

    // ---- shuffle epilogue: pair (i,f) with (g,o) via lane^1 ----
    float* H2 = smf + OFF_A;            // 16 units x H_STR (aliases A bufs)
    const int mymt = tig & 1;
    const int r0e = wm * 32 + mymt * 16 + gq;
    #pragma unroll
    for (int nt = 0; nt < 4; nt++) {
        const int u = wn * 8 + nt * 2 + (tig >> 1);
        float oth[4];
        #pragma unroll
        for (int e = 0; e < 4; e++)
            oth[e] = __shfl_xor_sync(0xffffffffu, acc[mymt ^ 1][nt][e], 1);
        const float b0 = smf[OFF_BIAS + 4 * u + 0];
        const float b1 = smf[OFF_BIAS + 4 * u + 1];
        const float b2 = smf[OFF_BIAS + 4 * u + 2];
        const float b3 = smf[OFF_BIAS + 4 * u + 3];
        #pragma unroll
        for (int e2 = 0; e2 < 2; e2++) {
            const float ow0 = acc[mymt][nt][2 * e2], ow1 = acc[mymt][nt][2 * e2 + 1];
            const float ot0 = oth[2 * e2],           ot1 = oth[2 * e2 + 1];
            float gi, gf, gg, go;
            if (mymt == 0) { gi = ow0; gf = ow1; gg = ot0; go = ot1; }
            else           { gg = ow0; go = ow1; gi = ot0; gf = ot1; }
            gi += b0; gf += b1; gg += b2; go += b3;
            const int row = r0e + 8 * e2;
            const size_t ci = (size_t)(j * 16 + u) * NB + n0 + row;
            const float cold = g_Cbuf[ci];
            const float cn = sigf(gf) * cold + sigf(gi) * tanhf_(gg);
            g_Cbuf[ci] = cn;
            H2[u * H_STR + row] = sigf(go) * tanhf_(cn);
        }
    }
    __syncthreads();

    // ---- h-state writeback (h-major, pre-rounded to tf32) ----
    #pragma unroll
    for (int q = 0; q < 2; q++) {
        const int u = wid * 2 + q;
        #pragma unroll
        for (int mk = 0; mk < 4; mk++) {
            const int m = mk * 32 + lane;
            hnext[(size_t)(j * 16 + u) * NB + n0 + m] =
                __uint_as_float(rna_tf32(H2[u * H_STR + m]));
        }
    }
    // ---- output: out[n][t][h], 64B contiguous (16 h per CTA) ----
    const int hh = lane & 15, rp = lane >> 4;
    #pragma unroll
    for (int i2 = 0; i2 < 8; i2++) {
        const int mr = wid * 16 + i2 * 2 + rp;
        out[(size_t)(n0 + mr) * TOUT * HD + (size_t)t_out * HD + j * 16 + hh] =
            H2[hh * H_STR + mr];
    }
}

// ---------------------------------------------------------------------------
// launch: prep + zprep (all-t img GEMM) + 114 K=128 recurrent steps
// ---------------------------------------------------------------------------
extern "C" void kernel_launch(void* const* d_in, const int* in_sizes, int n_in,
                              void* d_out, int out_size) {
    const float* img = (const float*)d_in[0];
    const float* Wih = (const float*)d_in[2];
    const float* Whh = (const float*)d_in[3];
    const float* bih = (const float*)d_in[4];
    const float* bhh = (const float*)d_in[5];
    float* out = (float*)d_out;

    const int T    = in_sizes[0] / (HD * NB);       // 60
    const int TOUT = out_size / (NB * HD);          // 114

    void *h0p, *h1p, *zp, *whhp, *wsump;
    cudaGetSymbolAddress(&h0p, g_Hbuf0);
    cudaGetSymbolAddress(&h1p, g_Hbuf1);
    cudaGetSymbolAddress(&zp, g_Z);
    cudaGetSymbolAddress(&whhp, g_Whh);
    cudaGetSymbolAddress(&wsump, g_Wsum);
    float* hb[2] = {(float*)h0p, (float*)h1p};

    cudaFuncSetAttribute((const void*)zprep_kernel,
                         cudaFuncAttributeMaxDynamicSharedMemorySize, SM_BYTES_PC);
    cudaFuncSetAttribute((const void*)lstm_step<true>,
                         cudaFuncAttributeMaxDynamicSharedMemorySize, SM_BYTES);
    cudaFuncSetAttribute((const void*)lstm_step<false>,
                         cudaFuncAttributeMaxDynamicSharedMemorySize, SM_BYTES);

    prep_kernel<<<256, 256>>>(Wih, Whh, bih, bhh);
    zprep_kernel<<<dim3(8, NB / 128, T), 256, SM_BYTES_PC>>>(img);

    dim3 grid(8, NB / 128);                         // 256 CTAs, 2/SM
    for (int t = 0; t < TOUT; t++) {
        float* hp = hb[t & 1];
        float* hn = hb[(t + 1) & 1];
        if (t < T) {
            lstm_step<true><<<grid, 256, SM_BYTES>>>(
                (const float*)zp + (size_t)t * NG * NB, (const float*)whhp,
                hp, hn, out, t, TOUT);
        } else {
            lstm_step<false><<<grid, 256, SM_BYTES>>>(
                nullptr, (const float*)wsump, hp, hn, out, t, TOUT);
        }
    }
}